// round 1
// baseline (speedup 1.0000x reference)
#include <cuda_runtime.h>
#include <math.h>

// Problem constants
#define B_SZ 2
#define S_SZ 2048
#define D_SZ 1024
#define H_SZ 16
#define DH   64
#define MROWS (B_SZ * S_SZ)   // 4096

// Scratch (device globals: allocation-free rule)
__device__ float g_Q[MROWS * D_SZ];
__device__ float g_K[MROWS * D_SZ];
__device__ float g_V[MROWS * D_SZ];
__device__ float g_A[MROWS * D_SZ];

// ---------------------------------------------------------------------------
// SGEMM body: C[M,N] = A[M,K] @ W[K,N] + bias[N]
// BM=BN=128, BK=16, 256 threads, 8x8 micro-tile per thread.
// ---------------------------------------------------------------------------
__device__ __forceinline__ void gemm_body(
    const float* __restrict__ A, const float* __restrict__ W,
    const float* __restrict__ bias, float* __restrict__ C,
    int M, int N, int K)
{
    __shared__ float As[16][132];   // transposed: As[k][m]
    __shared__ float Bs[16][128];   // natural:    Bs[k][n]

    const int tid = threadIdx.x;
    const int m0 = blockIdx.y * 128;
    const int n0 = blockIdx.x * 128;
    const int ty = tid >> 4, tx = tid & 15;
    const int r0 = ty * 8, c0 = tx * 8;

    float acc[8][8];
#pragma unroll
    for (int i = 0; i < 8; i++)
#pragma unroll
        for (int j = 0; j < 8; j++) acc[i][j] = 0.f;

    for (int k0 = 0; k0 < K; k0 += 16) {
        // Load A tile 128x16 (transposed into smem)
#pragma unroll
        for (int i = 0; i < 2; i++) {
            int f = tid + i * 256;
            int row = f >> 2;            // 0..127
            int fc  = (f & 3) * 4;       // 0,4,8,12
            float4 v = *(const float4*)&A[(size_t)(m0 + row) * K + k0 + fc];
            As[fc + 0][row] = v.x;
            As[fc + 1][row] = v.y;
            As[fc + 2][row] = v.z;
            As[fc + 3][row] = v.w;
        }
        // Load B tile 16x128
#pragma unroll
        for (int i = 0; i < 2; i++) {
            int f = tid + i * 256;
            int row = f >> 5;            // 0..15
            int fc  = (f & 31) * 4;      // 0..124
            *(float4*)&Bs[row][fc] =
                *(const float4*)&W[(size_t)(k0 + row) * N + n0 + fc];
        }
        __syncthreads();

#pragma unroll
        for (int kk = 0; kk < 16; kk++) {
            float a[8], b[8];
            *(float4*)&a[0] = *(const float4*)&As[kk][r0];
            *(float4*)&a[4] = *(const float4*)&As[kk][r0 + 4];
            *(float4*)&b[0] = *(const float4*)&Bs[kk][c0];
            *(float4*)&b[4] = *(const float4*)&Bs[kk][c0 + 4];
#pragma unroll
            for (int i = 0; i < 8; i++)
#pragma unroll
                for (int j = 0; j < 8; j++)
                    acc[i][j] = fmaf(a[i], b[j], acc[i][j]);
        }
        __syncthreads();
    }

    // Epilogue: bias + store
    float bb[8];
#pragma unroll
    for (int j = 0; j < 8; j++) bb[j] = bias[n0 + c0 + j];
#pragma unroll
    for (int i = 0; i < 8; i++) {
        float out[8];
#pragma unroll
        for (int j = 0; j < 8; j++) out[j] = acc[i][j] + bb[j];
        size_t off = (size_t)(m0 + r0 + i) * N + n0 + c0;
        *(float4*)&C[off]     = *(float4*)&out[0];
        *(float4*)&C[off + 4] = *(float4*)&out[4];
    }
}

__global__ __launch_bounds__(256) void qkv_kernel(
    const float* __restrict__ x,
    const float* __restrict__ Wq, const float* __restrict__ bq,
    const float* __restrict__ Wk, const float* __restrict__ bk,
    const float* __restrict__ Wv, const float* __restrict__ bv)
{
    const float* W;
    const float* b;
    float* C;
    if (blockIdx.z == 0)      { W = Wq; b = bq; C = g_Q; }
    else if (blockIdx.z == 1) { W = Wk; b = bk; C = g_K; }
    else                      { W = Wv; b = bv; C = g_V; }
    gemm_body(x, W, b, C, MROWS, D_SZ, D_SZ);
}

__global__ __launch_bounds__(256) void out_kernel(
    const float* __restrict__ Wo, const float* __restrict__ bo,
    float* __restrict__ out)
{
    gemm_body(g_A, Wo, bo, out, MROWS, D_SZ, D_SZ);
}

// ---------------------------------------------------------------------------
// Flash attention (causal, online softmax).
// Grid: (S/64, H, B), 128 threads. BQ=64, BKT=64, D=64.
// Thread tile: 4 rows x 8 cols (ty=tid/8 -> rows, tx=tid%8 -> cols).
// ---------------------------------------------------------------------------
#define PAD 68
#define ATTN_SMEM_FLOATS (64*PAD*2 + 64*64 + 64*8 + 64*3)

__global__ __launch_bounds__(128) void attn_kernel(
    const float* __restrict__ Q, const float* __restrict__ K,
    const float* __restrict__ V, float* __restrict__ O)
{
    extern __shared__ float sm[];
    float* QsT  = sm;                 // [d][q]  64 x PAD
    float* KPs  = QsT + 64 * PAD;     // KsT [d][k] / PsT [k][q]  64 x PAD
    float* Vs   = KPs + 64 * PAD;     // [k][d]  64 x 64
    float* red  = Vs + 64 * 64;       // [64][8]
    float* m_s  = red + 512;          // [64]
    float* l_s  = m_s + 64;           // [64]
    float* al_s = l_s + 64;           // [64]

    const int tid = threadIdx.x;
    const int qt = gridDim.x - 1 - blockIdx.x;   // heavy tiles first
    const int h  = blockIdx.y;
    const int b  = blockIdx.z;
    const int q0 = qt * 64;
    const int ty = tid >> 3, tx = tid & 7;
    const int r0 = ty * 4, c0 = tx * 8;

    const float* Qg = Q + ((size_t)b * S_SZ + q0) * D_SZ + h * DH;

    // Load Q tile transposed: QsT[d][q]
#pragma unroll
    for (int i = 0; i < 8; i++) {
        int f = tid + i * 128;
        int row = f >> 4;            // q row 0..63
        int fc  = (f & 15) * 4;      // d 0..60
        float4 v = *(const float4*)&Qg[(size_t)row * D_SZ + fc];
        QsT[(fc + 0) * PAD + row] = v.x;
        QsT[(fc + 1) * PAD + row] = v.y;
        QsT[(fc + 2) * PAD + row] = v.z;
        QsT[(fc + 3) * PAD + row] = v.w;
    }
    if (tid < 64) { m_s[tid] = -INFINITY; l_s[tid] = 0.f; }

    float o[4][8];
#pragma unroll
    for (int i = 0; i < 4; i++)
#pragma unroll
        for (int j = 0; j < 8; j++) o[i][j] = 0.f;

    for (int kt = 0; kt <= qt; kt++) {
        __syncthreads();   // protect KPs (prev PsT reads) + Q load + red reuse

        const float* Kg = K + ((size_t)b * S_SZ + kt * 64) * D_SZ + h * DH;
        const float* Vg = V + ((size_t)b * S_SZ + kt * 64) * D_SZ + h * DH;
#pragma unroll
        for (int i = 0; i < 8; i++) {
            int f = tid + i * 128;
            int row = f >> 4;
            int fc  = (f & 15) * 4;
            float4 kv = *(const float4*)&Kg[(size_t)row * D_SZ + fc];
            KPs[(fc + 0) * PAD + row] = kv.x;
            KPs[(fc + 1) * PAD + row] = kv.y;
            KPs[(fc + 2) * PAD + row] = kv.z;
            KPs[(fc + 3) * PAD + row] = kv.w;
            *(float4*)&Vs[row * 64 + fc] =
                *(const float4*)&Vg[(size_t)row * D_SZ + fc];
        }
        __syncthreads();

        // S = (Q K^T) * scale
        float s[4][8];
#pragma unroll
        for (int i = 0; i < 4; i++)
#pragma unroll
            for (int j = 0; j < 8; j++) s[i][j] = 0.f;

#pragma unroll 8
        for (int d = 0; d < 64; d++) {
            float a[4], bb[8];
            *(float4*)&a[0]  = *(const float4*)&QsT[d * PAD + r0];
            *(float4*)&bb[0] = *(const float4*)&KPs[d * PAD + c0];
            *(float4*)&bb[4] = *(const float4*)&KPs[d * PAD + c0 + 4];
#pragma unroll
            for (int i = 0; i < 4; i++)
#pragma unroll
                for (int j = 0; j < 8; j++)
                    s[i][j] = fmaf(a[i], bb[j], s[i][j]);
        }
        const float scale = 0.125f;   // 1/sqrt(64)
#pragma unroll
        for (int i = 0; i < 4; i++)
#pragma unroll
            for (int j = 0; j < 8; j++) s[i][j] *= scale;

        if (kt == qt) {               // causal mask within diagonal tile
#pragma unroll
            for (int i = 0; i < 4; i++)
#pragma unroll
                for (int j = 0; j < 8; j++)
                    if (c0 + j > r0 + i) s[i][j] = -INFINITY;
        }

        // Row-max partials
#pragma unroll
        for (int i = 0; i < 4; i++) {
            float pm = s[i][0];
#pragma unroll
            for (int j = 1; j < 8; j++) pm = fmaxf(pm, s[i][j]);
            red[(r0 + i) * 8 + tx] = pm;
        }
        __syncthreads();
        if (tid < 64) {
            float mo = m_s[tid];
            float mx = red[tid * 8];
#pragma unroll
            for (int j = 1; j < 8; j++) mx = fmaxf(mx, red[tid * 8 + j]);
            float mn = fmaxf(mo, mx);
            m_s[tid]  = mn;
            al_s[tid] = __expf(mo - mn);
        }
        __syncthreads();

        // P = exp(S - m), write transposed PsT[k][q], row-sum partials
#pragma unroll
        for (int i = 0; i < 4; i++) {
            float mn = m_s[r0 + i];
            float ps = 0.f;
#pragma unroll
            for (int j = 0; j < 8; j++) {
                float p = __expf(s[i][j] - mn);
                ps += p;
                KPs[(c0 + j) * PAD + (r0 + i)] = p;
            }
            red[(r0 + i) * 8 + tx] = ps;
        }
        __syncthreads();
        if (tid < 64) {
            float l = l_s[tid] * al_s[tid];
#pragma unroll
            for (int j = 0; j < 8; j++) l += red[tid * 8 + j];
            l_s[tid] = l;
        }
        __syncthreads();   // PsT visible to all before PV

        // O = O*alpha + P @ V
        float al[4];
#pragma unroll
        for (int i = 0; i < 4; i++) al[i] = al_s[r0 + i];
#pragma unroll
        for (int i = 0; i < 4; i++)
#pragma unroll
            for (int j = 0; j < 8; j++) o[i][j] *= al[i];

#pragma unroll 8
        for (int k = 0; k < 64; k++) {
            float a[4], bb[8];
            *(float4*)&a[0]  = *(const float4*)&KPs[k * PAD + r0];
            *(float4*)&bb[0] = *(const float4*)&Vs[k * 64 + c0];
            *(float4*)&bb[4] = *(const float4*)&Vs[k * 64 + c0 + 4];
#pragma unroll
            for (int i = 0; i < 4; i++)
#pragma unroll
                for (int j = 0; j < 8; j++)
                    o[i][j] = fmaf(a[i], bb[j], o[i][j]);
        }
    }

    // Final normalize + store to g_A layout [B,S,H*DV]
#pragma unroll
    for (int i = 0; i < 4; i++) {
        float inv = 1.f / l_s[r0 + i];
        int gr = q0 + r0 + i;
        float out[8];
#pragma unroll
        for (int j = 0; j < 8; j++) out[j] = o[i][j] * inv;
        float* Og = O + ((size_t)b * S_SZ + gr) * D_SZ + h * DH + c0;
        *(float4*)&Og[0] = *(float4*)&out[0];
        *(float4*)&Og[4] = *(float4*)&out[4];
    }
}

// ---------------------------------------------------------------------------

extern "C" void kernel_launch(void* const* d_in, const int* in_sizes, int n_in,
                              void* d_out, int out_size)
{
    const float* x  = (const float*)d_in[0];
    const float* Wq = (const float*)d_in[1];
    const float* bq = (const float*)d_in[2];
    const float* Wk = (const float*)d_in[3];
    const float* bk = (const float*)d_in[4];
    const float* Wv = (const float*)d_in[5];
    const float* bv = (const float*)d_in[6];
    const float* Wo = (const float*)d_in[7];
    const float* bo = (const float*)d_in[8];
    float* out = (float*)d_out;

    const int attn_smem = ATTN_SMEM_FLOATS * sizeof(float);
    cudaFuncSetAttribute(attn_kernel,
                         cudaFuncAttributeMaxDynamicSharedMemorySize, attn_smem);

    float* gq; cudaGetSymbolAddress((void**)&gq, g_Q);
    float* gk; cudaGetSymbolAddress((void**)&gk, g_K);
    float* gv; cudaGetSymbolAddress((void**)&gv, g_V);
    float* ga; cudaGetSymbolAddress((void**)&ga, g_A);

    // 1) fused QKV projections
    dim3 g1(D_SZ / 128, MROWS / 128, 3);
    qkv_kernel<<<g1, 256>>>(x, Wq, bq, Wk, bk, Wv, bv);

    // 2) causal flash attention -> g_A
    dim3 g2(S_SZ / 64, H_SZ, B_SZ);
    attn_kernel<<<g2, 128, attn_smem>>>(gq, gk, gv, ga);

    // 3) output projection
    dim3 g3(D_SZ / 128, MROWS / 128);
    out_kernel<<<g3, 256>>>(Wo, bo, out);
}

// round 2
// speedup vs baseline: 3.4497x; 3.4497x over previous
#include <cuda_runtime.h>
#include <math.h>

#define B_SZ 2
#define S_SZ 2048
#define D_SZ 1024
#define H_SZ 16
#define DH   64
#define MROWS (B_SZ * S_SZ)   // 4096

__device__ float g_Q[MROWS * D_SZ];
__device__ float g_K[MROWS * D_SZ];
__device__ float g_V[MROWS * D_SZ];
__device__ float g_A[MROWS * D_SZ];

// ---------------------------------------------------------------------------
// tf32 helpers
// ---------------------------------------------------------------------------
__device__ __forceinline__ unsigned f2tf(float f) {
    unsigned u;
    asm("cvt.rna.tf32.f32 %0, %1;" : "=r"(u) : "f"(f));
    return u;
}

__device__ __forceinline__ void mma_tf32(float d[4], const unsigned a[4],
                                         const unsigned b[2]) {
    asm("mma.sync.aligned.m16n8k8.row.col.f32.tf32.tf32.f32 "
        "{%0,%1,%2,%3},{%4,%5,%6,%7},{%8,%9},{%0,%1,%2,%3};"
        : "+f"(d[0]), "+f"(d[1]), "+f"(d[2]), "+f"(d[3])
        : "r"(a[0]), "r"(a[1]), "r"(a[2]), "r"(a[3]), "r"(b[0]), "r"(b[1]));
}

// ---------------------------------------------------------------------------
// tf32 GEMM: C[M,N] = A[M,K] @ W[K,N] + bias
// BM=BN=128, BK=32, 256 threads (8 warps, 2x4), warp tile 64x32.
// As: [m][36] (stride 36 == 4 mod 32, conflict-free A frags)
// Bs: [k][136] (stride 136 == 8 mod 32, conflict-free B frags)
// ---------------------------------------------------------------------------
#define GAPAD 36
#define GBPAD 136

__device__ __forceinline__ void gemm_tf32_body(
    const float* __restrict__ A, const float* __restrict__ W,
    const float* __restrict__ bias, float* __restrict__ C,
    int M, int N, int K)
{
    __shared__ unsigned As[128 * GAPAD];
    __shared__ unsigned Bs[32 * GBPAD];

    const int tid  = threadIdx.x;
    const int warp = tid >> 5, lane = tid & 31;
    const int lq = lane >> 2, lr = lane & 3;   // lane/4, lane%4
    const int m0 = blockIdx.y * 128;
    const int n0 = blockIdx.x * 128;
    const int wm = (warp >> 2) * 64;           // 2 warp rows
    const int wn = (warp & 3) * 32;            // 4 warp cols

    float acc[4][4][4];
#pragma unroll
    for (int i = 0; i < 4; i++)
#pragma unroll
        for (int j = 0; j < 4; j++)
#pragma unroll
            for (int v = 0; v < 4; v++) acc[i][j][v] = 0.f;

    for (int k0 = 0; k0 < K; k0 += 32) {
        // Stage A (128x32) natural [m][k], tf32-rounded
#pragma unroll
        for (int i = 0; i < 4; i++) {
            int f = tid + i * 256;
            int row = f >> 3, kc = (f & 7) * 4;
            float4 v = *(const float4*)&A[(size_t)(m0 + row) * K + k0 + kc];
            uint4 u = { f2tf(v.x), f2tf(v.y), f2tf(v.z), f2tf(v.w) };
            *(uint4*)&As[row * GAPAD + kc] = u;
        }
        // Stage B (32x128) natural [k][n]
#pragma unroll
        for (int i = 0; i < 4; i++) {
            int f = tid + i * 256;
            int kr = f >> 5, nc = (f & 31) * 4;
            float4 v = *(const float4*)&W[(size_t)(k0 + kr) * N + n0 + nc];
            uint4 u = { f2tf(v.x), f2tf(v.y), f2tf(v.z), f2tf(v.w) };
            *(uint4*)&Bs[kr * GBPAD + nc] = u;
        }
        __syncthreads();

#pragma unroll
        for (int ks = 0; ks < 4; ks++) {
            const int k8 = ks * 8;
            unsigned a[4][4], b[4][2];
#pragma unroll
            for (int mt = 0; mt < 4; mt++) {
                int r = wm + mt * 16 + lq;
                a[mt][0] = As[r * GAPAD + k8 + lr];
                a[mt][1] = As[(r + 8) * GAPAD + k8 + lr];
                a[mt][2] = As[r * GAPAD + k8 + 4 + lr];
                a[mt][3] = As[(r + 8) * GAPAD + k8 + 4 + lr];
            }
#pragma unroll
            for (int nt = 0; nt < 4; nt++) {
                int c = wn + nt * 8 + lq;
                b[nt][0] = Bs[(k8 + lr) * GBPAD + c];
                b[nt][1] = Bs[(k8 + 4 + lr) * GBPAD + c];
            }
#pragma unroll
            for (int mt = 0; mt < 4; mt++)
#pragma unroll
                for (int nt = 0; nt < 4; nt++)
                    mma_tf32(acc[mt][nt], a[mt], b[nt]);
        }
        __syncthreads();
    }

    // Epilogue
#pragma unroll
    for (int mt = 0; mt < 4; mt++) {
#pragma unroll
        for (int nt = 0; nt < 4; nt++) {
            int r = m0 + wm + mt * 16 + lq;
            int c = n0 + wn + nt * 8 + 2 * lr;
            float b0 = bias[c], b1 = bias[c + 1];
            float2 v0 = { acc[mt][nt][0] + b0, acc[mt][nt][1] + b1 };
            float2 v1 = { acc[mt][nt][2] + b0, acc[mt][nt][3] + b1 };
            *(float2*)&C[(size_t)r * N + c] = v0;
            *(float2*)&C[(size_t)(r + 8) * N + c] = v1;
        }
    }
}

__global__ __launch_bounds__(256) void qkv_kernel(
    const float* __restrict__ x,
    const float* __restrict__ Wq, const float* __restrict__ bq,
    const float* __restrict__ Wk, const float* __restrict__ bk,
    const float* __restrict__ Wv, const float* __restrict__ bv)
{
    const float* W; const float* b; float* C;
    if (blockIdx.z == 0)      { W = Wq; b = bq; C = g_Q; }
    else if (blockIdx.z == 1) { W = Wk; b = bk; C = g_K; }
    else                      { W = Wv; b = bv; C = g_V; }
    gemm_tf32_body(x, W, b, C, MROWS, D_SZ, D_SZ);
}

__global__ __launch_bounds__(256) void out_kernel(
    const float* __restrict__ Wo, const float* __restrict__ bo,
    float* __restrict__ out)
{
    gemm_tf32_body(g_A, Wo, bo, out, MROWS, D_SZ, D_SZ);
}

// ---------------------------------------------------------------------------
// tf32 flash attention. BQ=128 q rows/CTA, key tiles of 64, 8 warps.
// Each warp owns 16 q rows. Online softmax in registers.
// Qs/Ks/Ps stride 68 (==4 mod 32), Vs stride 72 (==8 mod 32).
// ---------------------------------------------------------------------------
#define QS_STR 68
#define VS_STR 72
#define SM_QS  0
#define SM_KS  (128 * QS_STR)              // 8704
#define SM_VS  (SM_KS + 64 * QS_STR)       // 13056
#define SM_PS  (SM_VS + 64 * VS_STR)       // 17664
#define ATTN_SMEM_U32 (SM_PS + 128 * QS_STR)   // 26368
#define ATTN_SMEM_BYTES (ATTN_SMEM_U32 * 4)    // 105472

__global__ __launch_bounds__(256) void attn_kernel(
    const float* __restrict__ Q, const float* __restrict__ K,
    const float* __restrict__ V, float* __restrict__ O)
{
    extern __shared__ unsigned sm[];
    unsigned* Qs = sm + SM_QS;
    unsigned* Ks = sm + SM_KS;
    unsigned* Vs = sm + SM_VS;
    unsigned* Ps = sm + SM_PS;

    const int tid  = threadIdx.x;
    const int warp = tid >> 5, lane = tid & 31;
    const int lq = lane >> 2, lr = lane & 3;
    const int qt = gridDim.x - 1 - blockIdx.x;   // heavy tiles first
    const int h  = blockIdx.y;
    const int b  = blockIdx.z;
    const int q0 = qt * 128;
    const int wq = warp * 16;                    // warp's q-row base (local)

    const float* Qg = Q + ((size_t)b * S_SZ + q0) * D_SZ + h * DH;

    // Stage Q (pre-scaled by 1/sqrt(dk)=0.125)
#pragma unroll
    for (int i = 0; i < 8; i++) {
        int f = tid + i * 256;
        int row = f >> 4, d = (f & 15) * 4;
        float4 v = *(const float4*)&Qg[(size_t)row * D_SZ + d];
        uint4 u = { f2tf(v.x * 0.125f), f2tf(v.y * 0.125f),
                    f2tf(v.z * 0.125f), f2tf(v.w * 0.125f) };
        *(uint4*)&Qs[row * QS_STR + d] = u;
    }

    float o[8][4];
#pragma unroll
    for (int dt = 0; dt < 8; dt++)
#pragma unroll
        for (int v = 0; v < 4; v++) o[dt][v] = 0.f;
    float m0v = -INFINITY, m1v = -INFINITY;
    float l0v = 0.f, l1v = 0.f;

    const int nkt = 2 * qt + 2;
    for (int kt = 0; kt < nkt; kt++) {
        __syncthreads();   // prior readers of Ks/Vs done (also covers Q stage)

        const float* Kg = K + ((size_t)b * S_SZ + kt * 64) * D_SZ + h * DH;
        const float* Vg = V + ((size_t)b * S_SZ + kt * 64) * D_SZ + h * DH;
#pragma unroll
        for (int i = 0; i < 4; i++) {
            int f = tid + i * 256;
            int row = f >> 4, d = (f & 15) * 4;
            float4 kv = *(const float4*)&Kg[(size_t)row * D_SZ + d];
            uint4 uk = { f2tf(kv.x), f2tf(kv.y), f2tf(kv.z), f2tf(kv.w) };
            *(uint4*)&Ks[row * QS_STR + d] = uk;
            float4 vv = *(const float4*)&Vg[(size_t)row * D_SZ + d];
            uint4 uv = { f2tf(vv.x), f2tf(vv.y), f2tf(vv.z), f2tf(vv.w) };
            *(uint4*)&Vs[row * VS_STR + d] = uv;
        }
        __syncthreads();

        // Warp fully above the diagonal for this key tile? skip compute.
        if (kt * 64 > q0 + wq + 15) continue;

        // ---- S = Q K^T (16 x 64 per warp) ----
        float s[8][4];
#pragma unroll
        for (int nt = 0; nt < 8; nt++)
#pragma unroll
            for (int v = 0; v < 4; v++) s[nt][v] = 0.f;

#pragma unroll
        for (int ks = 0; ks < 8; ks++) {
            const int k8 = ks * 8;
            unsigned a[4];
            int r = wq + lq;
            a[0] = Qs[r * QS_STR + k8 + lr];
            a[1] = Qs[(r + 8) * QS_STR + k8 + lr];
            a[2] = Qs[r * QS_STR + k8 + 4 + lr];
            a[3] = Qs[(r + 8) * QS_STR + k8 + 4 + lr];
#pragma unroll
            for (int nt = 0; nt < 8; nt++) {
                unsigned bf[2];
                int c = nt * 8 + lq;
                bf[0] = Ks[c * QS_STR + k8 + lr];
                bf[1] = Ks[c * QS_STR + k8 + 4 + lr];
                mma_tf32(s[nt], a, bf);
            }
        }

        // ---- causal mask (only near-diagonal tiles) ----
        if (kt >= 2 * qt) {
            int qr0 = q0 + wq + lq;
            int qr1 = qr0 + 8;
#pragma unroll
            for (int nt = 0; nt < 8; nt++) {
                int kb = kt * 64 + nt * 8 + 2 * lr;
                if (kb > qr0)     s[nt][0] = -INFINITY;
                if (kb + 1 > qr0) s[nt][1] = -INFINITY;
                if (kb > qr1)     s[nt][2] = -INFINITY;
                if (kb + 1 > qr1) s[nt][3] = -INFINITY;
            }
        }

        // ---- online softmax ----
        float mx0 = s[0][0], mx1 = s[0][2];
#pragma unroll
        for (int nt = 0; nt < 8; nt++) {
            mx0 = fmaxf(mx0, fmaxf(s[nt][0], s[nt][1]));
            mx1 = fmaxf(mx1, fmaxf(s[nt][2], s[nt][3]));
        }
        mx0 = fmaxf(mx0, __shfl_xor_sync(0xffffffff, mx0, 1));
        mx0 = fmaxf(mx0, __shfl_xor_sync(0xffffffff, mx0, 2));
        mx1 = fmaxf(mx1, __shfl_xor_sync(0xffffffff, mx1, 1));
        mx1 = fmaxf(mx1, __shfl_xor_sync(0xffffffff, mx1, 2));

        float mn0 = fmaxf(m0v, mx0), mn1 = fmaxf(m1v, mx1);
        float al0 = __expf(m0v - mn0), al1 = __expf(m1v - mn1);
        m0v = mn0; m1v = mn1;

        float ls0 = 0.f, ls1 = 0.f;
        int prow = wq + lq;
#pragma unroll
        for (int nt = 0; nt < 8; nt++) {
            float p0 = __expf(s[nt][0] - mn0);
            float p1 = __expf(s[nt][1] - mn0);
            float p2 = __expf(s[nt][2] - mn1);
            float p3 = __expf(s[nt][3] - mn1);
            ls0 += p0 + p1; ls1 += p2 + p3;
            int col = nt * 8 + 2 * lr;
            uint2 u0 = { f2tf(p0), f2tf(p1) };
            uint2 u1 = { f2tf(p2), f2tf(p3) };
            *(uint2*)&Ps[prow * QS_STR + col] = u0;
            *(uint2*)&Ps[(prow + 8) * QS_STR + col] = u1;
        }
        ls0 += __shfl_xor_sync(0xffffffff, ls0, 1);
        ls0 += __shfl_xor_sync(0xffffffff, ls0, 2);
        ls1 += __shfl_xor_sync(0xffffffff, ls1, 1);
        ls1 += __shfl_xor_sync(0xffffffff, ls1, 2);
        l0v = l0v * al0 + ls0;
        l1v = l1v * al1 + ls1;

#pragma unroll
        for (int dt = 0; dt < 8; dt++) {
            o[dt][0] *= al0; o[dt][1] *= al0;
            o[dt][2] *= al1; o[dt][3] *= al1;
        }
        __syncwarp();   // Ps visible across the warp

        // ---- O += P V ----
#pragma unroll
        for (int ks = 0; ks < 8; ks++) {
            const int k8 = ks * 8;
            unsigned a[4];
            int r = wq + lq;
            a[0] = Ps[r * QS_STR + k8 + lr];
            a[1] = Ps[(r + 8) * QS_STR + k8 + lr];
            a[2] = Ps[r * QS_STR + k8 + 4 + lr];
            a[3] = Ps[(r + 8) * QS_STR + k8 + 4 + lr];
#pragma unroll
            for (int dt = 0; dt < 8; dt++) {
                unsigned bf[2];
                int c = dt * 8 + lq;
                bf[0] = Vs[(k8 + lr) * VS_STR + c];
                bf[1] = Vs[(k8 + 4 + lr) * VS_STR + c];
                mma_tf32(o[dt], a, bf);
            }
        }
        __syncwarp();   // all lanes done reading Ps before next overwrite
    }

    // ---- epilogue: normalize + store ----
    float inv0 = 1.f / l0v, inv1 = 1.f / l1v;
    int gr0 = q0 + wq + lq;
#pragma unroll
    for (int dt = 0; dt < 8; dt++) {
        int col = dt * 8 + 2 * lr;
        float2 v0 = { o[dt][0] * inv0, o[dt][1] * inv0 };
        float2 v1 = { o[dt][2] * inv1, o[dt][3] * inv1 };
        *(float2*)&O[((size_t)b * S_SZ + gr0) * D_SZ + h * DH + col] = v0;
        *(float2*)&O[((size_t)b * S_SZ + gr0 + 8) * D_SZ + h * DH + col] = v1;
    }
}

// ---------------------------------------------------------------------------

extern "C" void kernel_launch(void* const* d_in, const int* in_sizes, int n_in,
                              void* d_out, int out_size)
{
    const float* x  = (const float*)d_in[0];
    const float* Wq = (const float*)d_in[1];
    const float* bq = (const float*)d_in[2];
    const float* Wk = (const float*)d_in[3];
    const float* bk = (const float*)d_in[4];
    const float* Wv = (const float*)d_in[5];
    const float* bv = (const float*)d_in[6];
    const float* Wo = (const float*)d_in[7];
    const float* bo = (const float*)d_in[8];
    float* out = (float*)d_out;

    cudaFuncSetAttribute(attn_kernel,
                         cudaFuncAttributeMaxDynamicSharedMemorySize,
                         ATTN_SMEM_BYTES);

    float* gq; cudaGetSymbolAddress((void**)&gq, g_Q);
    float* gk; cudaGetSymbolAddress((void**)&gk, g_K);
    float* gv; cudaGetSymbolAddress((void**)&gv, g_V);
    float* ga; cudaGetSymbolAddress((void**)&ga, g_A);

    dim3 g1(D_SZ / 128, MROWS / 128, 3);
    qkv_kernel<<<g1, 256>>>(x, Wq, bq, Wk, bk, Wv, bv);

    dim3 g2(S_SZ / 128, H_SZ, B_SZ);
    attn_kernel<<<g2, 256, ATTN_SMEM_BYTES>>>(gq, gk, gv, ga);

    dim3 g3(D_SZ / 128, MROWS / 128);
    out_kernel<<<g3, 256>>>(Wo, bo, out);
}

// round 4
// speedup vs baseline: 3.7942x; 1.0999x over previous
#include <cuda_runtime.h>
#include <math.h>

#define B_SZ 2
#define S_SZ 2048
#define D_SZ 1024
#define H_SZ 16
#define DH   64
#define MROWS (B_SZ * S_SZ)   // 4096

// Scratch (device globals: allocation-free rule)
__device__ float g_Q[MROWS * D_SZ];
__device__ float g_K[MROWS * D_SZ];
__device__ float g_V[MROWS * D_SZ];
__device__ float g_A[MROWS * D_SZ];
__device__ float g_XR[MROWS * D_SZ];      // tf32-rounded x
__device__ float g_WQ[D_SZ * D_SZ];
__device__ float g_WK[D_SZ * D_SZ];
__device__ float g_WV[D_SZ * D_SZ];
__device__ float g_WO[D_SZ * D_SZ];

// ---------------------------------------------------------------------------
// helpers
// ---------------------------------------------------------------------------
__device__ __forceinline__ unsigned f2tf(float f) {
    unsigned u;
    asm("cvt.rna.tf32.f32 %0, %1;" : "=r"(u) : "f"(f));
    return u;
}
__device__ __forceinline__ float tfr(float f) { return __uint_as_float(f2tf(f)); }

__device__ __forceinline__ void mma_tf32(float d[4], const unsigned a[4],
                                         const unsigned b[2]) {
    asm("mma.sync.aligned.m16n8k8.row.col.f32.tf32.tf32.f32 "
        "{%0,%1,%2,%3},{%4,%5,%6,%7},{%8,%9},{%0,%1,%2,%3};"
        : "+f"(d[0]), "+f"(d[1]), "+f"(d[2]), "+f"(d[3])
        : "r"(a[0]), "r"(a[1]), "r"(a[2]), "r"(a[3]), "r"(b[0]), "r"(b[1]));
}

__device__ __forceinline__ void cp16(unsigned* smem_dst, const void* g) {
    unsigned sa = (unsigned)__cvta_generic_to_shared(smem_dst);
    asm volatile("cp.async.cg.shared.global [%0], [%1], 16;\n" :: "r"(sa), "l"(g));
}
#define CP_COMMIT() asm volatile("cp.async.commit_group;\n")
#define CP_WAIT(n)  asm volatile("cp.async.wait_group %0;\n" :: "n"(n))

// ---------------------------------------------------------------------------
// preround: x,W -> tf32-rounded copies (float4 grid-stride)
// ---------------------------------------------------------------------------
#define X_F4 (MROWS * D_SZ / 4)          // 1048576
#define W_F4 (D_SZ * D_SZ / 4)           // 262144
#define PR_TOTAL (X_F4 + 4 * W_F4)       // 2097152

__global__ __launch_bounds__(256) void preround_kernel(
    const float* __restrict__ x,
    const float* __restrict__ wq, const float* __restrict__ wk,
    const float* __restrict__ wv, const float* __restrict__ wo)
{
    int i = blockIdx.x * blockDim.x + threadIdx.x;
    if (i >= PR_TOTAL) return;
    const float4* src; float4* dst; int off;
    if (i < X_F4)               { src = (const float4*)x;  dst = (float4*)g_XR; off = i; }
    else if (i < X_F4 + W_F4)   { src = (const float4*)wq; dst = (float4*)g_WQ; off = i - X_F4; }
    else if (i < X_F4 + 2*W_F4) { src = (const float4*)wk; dst = (float4*)g_WK; off = i - X_F4 - W_F4; }
    else if (i < X_F4 + 3*W_F4) { src = (const float4*)wv; dst = (float4*)g_WV; off = i - X_F4 - 2*W_F4; }
    else                        { src = (const float4*)wo; dst = (float4*)g_WO; off = i - X_F4 - 3*W_F4; }
    float4 v = src[off];
    float4 r = { tfr(v.x), tfr(v.y), tfr(v.z), tfr(v.w) };
    dst[off] = r;
}

// ---------------------------------------------------------------------------
// tf32 GEMM, cp.async 3-stage pipeline.
// BM=BN=128, BK=32, 256 threads (8 warps 2x4), warp tile 64x32.
// As stride 36 (==4 mod 32), Bs stride 136 (==8 mod 32): conflict-free frags.
// ---------------------------------------------------------------------------
#define GAPAD 36
#define GBPAD 136
#define AS_U32 (128 * GAPAD)                 // 4608
#define BS_U32 (32 * GBPAD)                  // 4352
#define STAGE_U32 (AS_U32 + BS_U32)          // 8960
#define GEMM_SMEM (3 * STAGE_U32 * 4)        // 107520 B

template<bool ROUND>
__device__ __forceinline__ void gemm_cp(
    const float* __restrict__ A, const float* __restrict__ W,
    const float* __restrict__ bias, float* __restrict__ C, int N, int K)
{
    extern __shared__ unsigned sm[];
    const int tid  = threadIdx.x;
    const int warp = tid >> 5, lane = tid & 31;
    const int lq = lane >> 2, lr = lane & 3;
    const int m0 = blockIdx.y * 128;
    const int n0 = blockIdx.x * 128;
    const int wm = (warp >> 2) * 64;
    const int wn = (warp & 3) * 32;

    float acc[4][4][4];
#pragma unroll
    for (int i = 0; i < 4; i++)
#pragma unroll
        for (int j = 0; j < 4; j++)
#pragma unroll
            for (int v = 0; v < 4; v++) acc[i][j][v] = 0.f;

    const int T = K / 32;

    auto issue = [&](int t) {
        unsigned* As = sm + (t % 3) * STAGE_U32;
        unsigned* Bs = As + AS_U32;
        const int k0 = t * 32;
#pragma unroll
        for (int i = 0; i < 4; i++) {
            int f = tid + i * 256;
            int row = f >> 3, c = (f & 7) * 4;
            cp16(&As[row * GAPAD + c], &A[(size_t)(m0 + row) * K + k0 + c]);
        }
#pragma unroll
        for (int i = 0; i < 4; i++) {
            int f = tid + i * 256;
            int kr = f >> 5, nc = (f & 31) * 4;
            cp16(&Bs[kr * GBPAD + nc], &W[(size_t)(k0 + kr) * N + n0 + nc]);
        }
    };

    issue(0); CP_COMMIT();
    issue(1); CP_COMMIT();

    for (int t = 0; t < T; t++) {
        CP_WAIT(1);
        __syncthreads();
        if (t + 2 < T) issue(t + 2);
        CP_COMMIT();

        const unsigned* As = sm + (t % 3) * STAGE_U32;
        const unsigned* Bs = As + AS_U32;
#pragma unroll
        for (int ks = 0; ks < 4; ks++) {
            const int k8 = ks * 8;
            unsigned a[4][4], b[4][2];
#pragma unroll
            for (int mt = 0; mt < 4; mt++) {
                int r = wm + mt * 16 + lq;
                a[mt][0] = As[r * GAPAD + k8 + lr];
                a[mt][1] = As[(r + 8) * GAPAD + k8 + lr];
                a[mt][2] = As[r * GAPAD + k8 + 4 + lr];
                a[mt][3] = As[(r + 8) * GAPAD + k8 + 4 + lr];
            }
#pragma unroll
            for (int nt = 0; nt < 4; nt++) {
                int c = wn + nt * 8 + lq;
                b[nt][0] = Bs[(k8 + lr) * GBPAD + c];
                b[nt][1] = Bs[(k8 + 4 + lr) * GBPAD + c];
            }
#pragma unroll
            for (int mt = 0; mt < 4; mt++)
#pragma unroll
                for (int nt = 0; nt < 4; nt++)
                    mma_tf32(acc[mt][nt], a[mt], b[nt]);
        }
    }

    // Epilogue
#pragma unroll
    for (int mt = 0; mt < 4; mt++) {
#pragma unroll
        for (int nt = 0; nt < 4; nt++) {
            int r = m0 + wm + mt * 16 + lq;
            int c = n0 + wn + nt * 8 + 2 * lr;
            float b0 = bias[c], b1 = bias[c + 1];
            float2 v0, v1;
            if (ROUND) {
                v0 = { tfr(acc[mt][nt][0] + b0), tfr(acc[mt][nt][1] + b1) };
                v1 = { tfr(acc[mt][nt][2] + b0), tfr(acc[mt][nt][3] + b1) };
            } else {
                v0 = { acc[mt][nt][0] + b0, acc[mt][nt][1] + b1 };
                v1 = { acc[mt][nt][2] + b0, acc[mt][nt][3] + b1 };
            }
            *(float2*)&C[(size_t)r * N + c] = v0;
            *(float2*)&C[(size_t)(r + 8) * N + c] = v1;
        }
    }
}

__global__ __launch_bounds__(256) void qkv_kernel(
    const float* __restrict__ bq, const float* __restrict__ bk,
    const float* __restrict__ bv)
{
    const float* W; const float* b; float* C;
    if (blockIdx.z == 0)      { W = g_WQ; b = bq; C = g_Q; }
    else if (blockIdx.z == 1) { W = g_WK; b = bk; C = g_K; }
    else                      { W = g_WV; b = bv; C = g_V; }
    gemm_cp<true>(g_XR, W, b, C, D_SZ, D_SZ);
}

__global__ __launch_bounds__(256) void out_kernel(
    const float* __restrict__ bo, float* __restrict__ out)
{
    gemm_cp<false>(g_A, g_WO, bo, out, D_SZ, D_SZ);
}

// ---------------------------------------------------------------------------
// tf32 flash attention, cp.async double-buffered K/V, P kept in registers
// (accumulator -> A-fragment permute via width-4 shuffles).
// BQ=128, key tile 64, 8 warps x 16 q rows.
// ---------------------------------------------------------------------------
#define AQ_STR 68   // Qs/Ks stride (==4 mod 32)
#define AV_STR 72   // Vs stride   (==8 mod 32)
#define A_QS 0
#define A_KS (128 * AQ_STR)                      // 8704
#define A_VS (A_KS + 2 * 64 * AQ_STR)            // 17408
#define ATTN_SMEM ((A_VS + 2 * 64 * AV_STR) * 4) // 106496 B

__global__ __launch_bounds__(256, 2) void attn_kernel(
    const float* __restrict__ Q, const float* __restrict__ K,
    const float* __restrict__ V, float* __restrict__ O)
{
    extern __shared__ unsigned sm[];
    unsigned* Qs = sm + A_QS;

    const int tid  = threadIdx.x;
    const int warp = tid >> 5, lane = tid & 31;
    const int lq = lane >> 2, lr = lane & 3;
    const int qt = gridDim.x - 1 - blockIdx.x;   // heavy tiles first
    const int h  = blockIdx.y;
    const int b  = blockIdx.z;
    const int q0 = qt * 128;
    const int wq = warp * 16;

    const float* Qg = Q + ((size_t)b * S_SZ + q0) * D_SZ + h * DH;

    // Stage Q (pre-scaled by 1/sqrt(dk)=0.125, re-rounded)
#pragma unroll
    for (int i = 0; i < 8; i++) {
        int f = tid + i * 256;
        int row = f >> 4, d = (f & 15) * 4;
        float4 v = *(const float4*)&Qg[(size_t)row * D_SZ + d];
        uint4 u = { f2tf(v.x * 0.125f), f2tf(v.y * 0.125f),
                    f2tf(v.z * 0.125f), f2tf(v.w * 0.125f) };
        *(uint4*)&Qs[row * AQ_STR + d] = u;
    }

    auto issue_kv = [&](int kt) {
        int st = kt & 1;
        unsigned* Ks = sm + A_KS + st * (64 * AQ_STR);
        unsigned* Vs = sm + A_VS + st * (64 * AV_STR);
        const float* Kg = K + ((size_t)b * S_SZ + kt * 64) * D_SZ + h * DH;
        const float* Vg = V + ((size_t)b * S_SZ + kt * 64) * D_SZ + h * DH;
#pragma unroll
        for (int i = 0; i < 4; i++) {
            int f = tid + i * 256;
            int row = f >> 4, d = (f & 15) * 4;
            cp16(&Ks[row * AQ_STR + d], &Kg[(size_t)row * D_SZ + d]);
            cp16(&Vs[row * AV_STR + d], &Vg[(size_t)row * D_SZ + d]);
        }
    };

    float o[8][4];
#pragma unroll
    for (int dt = 0; dt < 8; dt++)
#pragma unroll
        for (int v = 0; v < 4; v++) o[dt][v] = 0.f;
    float m0v = -INFINITY, m1v = -INFINITY;
    float l0v = 0.f, l1v = 0.f;

    const int nkt = 2 * qt + 2;
    issue_kv(0); CP_COMMIT();

    const int hsel = lr >> 1, esel = lr & 1;

    for (int kt = 0; kt < nkt; kt++) {
        CP_WAIT(0);
        __syncthreads();                 // stage kt data ready; prev readers done
        if (kt + 1 < nkt) issue_kv(kt + 1);
        CP_COMMIT();

        if (kt * 64 <= q0 + wq + 15) {   // warp has unmasked rows in this tile
            const unsigned* Ks = sm + A_KS + (kt & 1) * (64 * AQ_STR);
            const unsigned* Vs = sm + A_VS + (kt & 1) * (64 * AV_STR);

            // ---- S = Q K^T (16 x 64 per warp) ----
            float s[8][4];
#pragma unroll
            for (int nt = 0; nt < 8; nt++)
#pragma unroll
                for (int v = 0; v < 4; v++) s[nt][v] = 0.f;

#pragma unroll
            for (int ks = 0; ks < 8; ks++) {
                const int k8 = ks * 8;
                unsigned a[4];
                int r = wq + lq;
                a[0] = Qs[r * AQ_STR + k8 + lr];
                a[1] = Qs[(r + 8) * AQ_STR + k8 + lr];
                a[2] = Qs[r * AQ_STR + k8 + 4 + lr];
                a[3] = Qs[(r + 8) * AQ_STR + k8 + 4 + lr];
#pragma unroll
                for (int nt = 0; nt < 8; nt++) {
                    unsigned bf[2];
                    int c = nt * 8 + lq;
                    bf[0] = Ks[c * AQ_STR + k8 + lr];
                    bf[1] = Ks[c * AQ_STR + k8 + 4 + lr];
                    mma_tf32(s[nt], a, bf);
                }
            }

            // ---- causal mask ----
            if (kt >= 2 * qt) {
                int qr0 = q0 + wq + lq, qr1 = qr0 + 8;
#pragma unroll
                for (int nt = 0; nt < 8; nt++) {
                    int kb = kt * 64 + nt * 8 + 2 * lr;
                    if (kb > qr0)     s[nt][0] = -INFINITY;
                    if (kb + 1 > qr0) s[nt][1] = -INFINITY;
                    if (kb > qr1)     s[nt][2] = -INFINITY;
                    if (kb + 1 > qr1) s[nt][3] = -INFINITY;
                }
            }

            // ---- online softmax ----
            float mx0 = s[0][0], mx1 = s[0][2];
#pragma unroll
            for (int nt = 0; nt < 8; nt++) {
                mx0 = fmaxf(mx0, fmaxf(s[nt][0], s[nt][1]));
                mx1 = fmaxf(mx1, fmaxf(s[nt][2], s[nt][3]));
            }
            mx0 = fmaxf(mx0, __shfl_xor_sync(0xffffffff, mx0, 1));
            mx0 = fmaxf(mx0, __shfl_xor_sync(0xffffffff, mx0, 2));
            mx1 = fmaxf(mx1, __shfl_xor_sync(0xffffffff, mx1, 1));
            mx1 = fmaxf(mx1, __shfl_xor_sync(0xffffffff, mx1, 2));

            float mn0 = fmaxf(m0v, mx0), mn1 = fmaxf(m1v, mx1);
            float al0 = __expf(m0v - mn0), al1 = __expf(m1v - mn1);
            m0v = mn0; m1v = mn1;

            float ls0 = 0.f, ls1 = 0.f;
#pragma unroll
            for (int nt = 0; nt < 8; nt++) {
                float p0 = __expf(s[nt][0] - mn0);
                float p1 = __expf(s[nt][1] - mn0);
                float p2 = __expf(s[nt][2] - mn1);
                float p3 = __expf(s[nt][3] - mn1);
                ls0 += p0 + p1; ls1 += p2 + p3;
                s[nt][0] = __uint_as_float(f2tf(p0));
                s[nt][1] = __uint_as_float(f2tf(p1));
                s[nt][2] = __uint_as_float(f2tf(p2));
                s[nt][3] = __uint_as_float(f2tf(p3));
            }
            ls0 += __shfl_xor_sync(0xffffffff, ls0, 1);
            ls0 += __shfl_xor_sync(0xffffffff, ls0, 2);
            ls1 += __shfl_xor_sync(0xffffffff, ls1, 1);
            ls1 += __shfl_xor_sync(0xffffffff, ls1, 2);
            l0v = l0v * al0 + ls0;
            l1v = l1v * al1 + ls1;

#pragma unroll
            for (int dt = 0; dt < 8; dt++) {
                o[dt][0] *= al0; o[dt][1] *= al0;
                o[dt][2] *= al1; o[dt][3] *= al1;
            }

            // ---- O += P V : A-frag from accumulator via width-4 shuffles ----
#pragma unroll
            for (int ks = 0; ks < 8; ks++) {
                float x0 = __shfl_sync(0xffffffff, s[ks][0], hsel, 4);
                float x1 = __shfl_sync(0xffffffff, s[ks][1], hsel, 4);
                float x2 = __shfl_sync(0xffffffff, s[ks][2], hsel, 4);
                float x3 = __shfl_sync(0xffffffff, s[ks][3], hsel, 4);
                float y0 = __shfl_sync(0xffffffff, s[ks][0], hsel + 2, 4);
                float y1 = __shfl_sync(0xffffffff, s[ks][1], hsel + 2, 4);
                float y2 = __shfl_sync(0xffffffff, s[ks][2], hsel + 2, 4);
                float y3 = __shfl_sync(0xffffffff, s[ks][3], hsel + 2, 4);
                unsigned a[4];
                a[0] = __float_as_uint(esel ? x1 : x0);
                a[1] = __float_as_uint(esel ? x3 : x2);
                a[2] = __float_as_uint(esel ? y1 : y0);
                a[3] = __float_as_uint(esel ? y3 : y2);
                const int k8 = ks * 8;
#pragma unroll
                for (int dt = 0; dt < 8; dt++) {
                    unsigned bf[2];
                    int c = dt * 8 + lq;
                    bf[0] = Vs[(k8 + lr) * AV_STR + c];
                    bf[1] = Vs[(k8 + 4 + lr) * AV_STR + c];
                    mma_tf32(o[dt], a, bf);
                }
            }
        }
    }

    // ---- epilogue: normalize + store (rounded: feeds out-proj cp.async) ----
    float inv0 = 1.f / l0v, inv1 = 1.f / l1v;
    int gr0 = q0 + wq + lq;
#pragma unroll
    for (int dt = 0; dt < 8; dt++) {
        int col = dt * 8 + 2 * lr;
        float2 v0 = { tfr(o[dt][0] * inv0), tfr(o[dt][1] * inv0) };
        float2 v1 = { tfr(o[dt][2] * inv1), tfr(o[dt][3] * inv1) };
        *(float2*)&O[((size_t)b * S_SZ + gr0) * D_SZ + h * DH + col] = v0;
        *(float2*)&O[((size_t)b * S_SZ + gr0 + 8) * D_SZ + h * DH + col] = v1;
    }
}

// ---------------------------------------------------------------------------

extern "C" void kernel_launch(void* const* d_in, const int* in_sizes, int n_in,
                              void* d_out, int out_size)
{
    const float* x  = (const float*)d_in[0];
    const float* Wq = (const float*)d_in[1];
    const float* bq = (const float*)d_in[2];
    const float* Wk = (const float*)d_in[3];
    const float* bk = (const float*)d_in[4];
    const float* Wv = (const float*)d_in[5];
    const float* bv = (const float*)d_in[6];
    const float* Wo = (const float*)d_in[7];
    const float* bo = (const float*)d_in[8];
    float* out = (float*)d_out;

    cudaFuncSetAttribute(qkv_kernel,
                         cudaFuncAttributeMaxDynamicSharedMemorySize, GEMM_SMEM);
    cudaFuncSetAttribute(out_kernel,
                         cudaFuncAttributeMaxDynamicSharedMemorySize, GEMM_SMEM);
    cudaFuncSetAttribute(attn_kernel,
                         cudaFuncAttributeMaxDynamicSharedMemorySize, ATTN_SMEM);

    float* gq; cudaGetSymbolAddress((void**)&gq, g_Q);
    float* gk; cudaGetSymbolAddress((void**)&gk, g_K);
    float* gv; cudaGetSymbolAddress((void**)&gv, g_V);
    float* ga; cudaGetSymbolAddress((void**)&ga, g_A);

    // 0) tf32 pre-round of x and weights
    preround_kernel<<<(PR_TOTAL + 255) / 256, 256>>>(x, Wq, Wk, Wv, Wo);

    // 1) fused QKV projections (rounded epilogue)
    dim3 g1(D_SZ / 128, MROWS / 128, 3);
    qkv_kernel<<<g1, 256, GEMM_SMEM>>>(bq, bk, bv);

    // 2) causal flash attention -> g_A (rounded epilogue)
    dim3 g2(S_SZ / 128, H_SZ, B_SZ);
    attn_kernel<<<g2, 256, ATTN_SMEM>>>(gq, gk, gv, ga);

    // 3) output projection (fp32 epilogue)
    dim3 g3(D_SZ / 128, MROWS / 128);
    out_kernel<<<g3, 256, GEMM_SMEM>>>(bo, out);
}